// round 16
// baseline (speedup 1.0000x reference)
#include <cuda_runtime.h>
#include <cuda_fp16.h>

#define T_STEPS 256
#define NN      64
#define HH      512
#define DT_C    0.01f
#define NBLK    256
#define NTHR    512
#define NWARP   16
#define RPW     16                                  // j-rows per warp (256-i wide)
#define RES_X   10                                  // resident Wx rows per warp
#define DYN_SMEM (NWARP * RES_X * 32 * 16)          // 16*10*512 = 81920 B

// fp16 transposed weights: layout [n][j][i]
__device__ __half g_Wh[(size_t)NN * HH * HH];
__device__ __half g_Wx[(size_t)NN * HH * HH];
// partial-sum exchange, parity double-buffered: [par][n][c][i]
__device__ float g_partial[2 * NN * 4 * HH];
__device__ unsigned g_chunk_cnt[4 * 32];   // per-chunk hy counters (128B apart)
__device__ unsigned g_part_cnt[NN];        // +4 per neuron per step

// ---------------------------------------------------------------------------
__device__ __forceinline__ void arrive_rel(unsigned* ctr)
{
    asm volatile("red.release.gpu.add.u32 [%0], 1;" :: "l"(ctr) : "memory");
}
__device__ __forceinline__ unsigned ld_acq(unsigned* ctr)
{
    unsigned v;
    asm volatile("ld.acquire.gpu.u32 %0, [%1];" : "=r"(v) : "l"(ctr) : "memory");
    return v;
}
__device__ __forceinline__ void spin_until(unsigned* ctr, unsigned target)
{
    if (ld_acq(ctr) >= target) return;
    while (ld_acq(ctr) < target) __nanosleep(20);
}

// ---------------------------------------------------------------------------
// fp32 [n][i][j]  ->  fp16 [n][j][i]   (transpose + convert, tiled)
// ---------------------------------------------------------------------------
__global__ void convert_transpose_kernel(const float* __restrict__ src, int which)
{
    __shared__ float tile[32][33];
    __half* dst = which ? g_Wx : g_Wh;
    const int nmat = blockIdx.z;
    const float* s = src + (size_t)nmat * HH * HH;
    __half*      d = dst + (size_t)nmat * HH * HH;
    const int x0 = blockIdx.x * 32;
    const int y0 = blockIdx.y * 32;
    #pragma unroll
    for (int k = threadIdx.y; k < 32; k += 8)
        tile[k][threadIdx.x] = s[(size_t)(y0 + k) * HH + x0 + threadIdx.x];
    __syncthreads();
    #pragma unroll
    for (int k = threadIdx.y; k < 32; k += 8)
        d[(size_t)(x0 + k) * HH + y0 + threadIdx.x] = __float2half_rn(tile[threadIdx.x][k]);
}

// ---------------------------------------------------------------------------
__global__ void init_out_kernel(const float* __restrict__ x,
                                const float* __restrict__ init_states,
                                float* __restrict__ states,
                                float* __restrict__ ins)
{
    const int i = blockIdx.x * blockDim.x + threadIdx.x;
    if (i < NN * 2 * HH) states[i] = init_states[i];
    if (i < NN * HH)     ins[i]    = x[i];
    if (i < NN)          g_part_cnt[i] = 0;
    if (i < 4 * 32)      g_chunk_cnt[i] = 0;
}

// ---------------------------------------------------------------------------
__device__ __forceinline__ void fma8(float* acc, uint4 a, float v)
{
    float2 f;
    f = __half22float2(*reinterpret_cast<__half2*>(&a.x)); acc[0] += f.x * v; acc[1] += f.y * v;
    f = __half22float2(*reinterpret_cast<__half2*>(&a.y)); acc[2] += f.x * v; acc[3] += f.y * v;
    f = __half22float2(*reinterpret_cast<__half2*>(&a.z)); acc[4] += f.x * v; acc[5] += f.y * v;
    f = __half22float2(*reinterpret_cast<__half2*>(&a.w)); acc[6] += f.x * v; acc[7] += f.y * v;
}

// ---------------------------------------------------------------------------
// persistent RNN, fully j-partitioned (R15 topology): 256 blocks = 4 per
// neuron, 2 blocks/SM, 512 threads.  Warp w = (ig = w>>3, jg = w&7) covers
// 16 j-rows x 256 i-outputs (acc[8]); single-round reduce over 8 partials.
// R16: 4 streamed-Wx loads hoisted above the ins-combine; chunk counter
// published early via named barrier among the combine warps.
// ---------------------------------------------------------------------------
__global__ void __launch_bounds__(NTHR, 2) rnn_kernel(
    const float* __restrict__ x,      // [T][N][H]
    const float* __restrict__ C,      // [N][N]
    const float* __restrict__ b,      // [N][H]
    float* __restrict__ states,       // [T+1][N][2][H]
    float* __restrict__ ins)          // [T+1][N][H]
{
    extern __shared__ __align__(16) unsigned char dynsmem[];
    uint4* sres = reinterpret_cast<uint4*>(dynsmem);

    __shared__ __align__(16) float sh_red[NWARP * 256];  // 16 KB reduce buffer
    __shared__ float sh_hy[128];
    __shared__ float sh_ins[128];
    __shared__ float sh_C[NN];
    __shared__ float sh_cm[4 * 128];

    const int bid  = blockIdx.x;
    const int n    = bid >> 2;
    const int c    = bid & 3;
    const int cb   = c * 128;
    const int tid  = threadIdx.x;
    const int w    = tid >> 5;
    const int lane = tid & 31;
    const int ig   = w >> 3;          // i-half: 0 or 1 (256 outputs)
    const int jg   = w & 7;           // j-group: 16 rows

    if (tid < NN) sh_C[tid] = C[n * NN + tid];
    const float bias = (tid < 128) ? b[n * HH + cb + tid] : 0.0f;
    float hz_r = (tid < 128) ? states[(n * 2 + 1) * HH + cb + tid] : 0.0f;
    if (tid < 128) sh_hy[tid] = states[(n * 2 + 0) * HH + cb + tid];
    float xv = (tid < 128) ? x[(size_t)n * HH + cb + tid] : 0.0f;

    // warp (ig,jg): j-rows cb + jg*16 .. +15, i-range ig*256 + lane*8
    const __half* pWh = g_Wh + (size_t)n * HH * HH + (size_t)(cb + jg * RPW) * HH + ig * 256 + lane * 8;
    const __half* pWx = g_Wx + (size_t)n * HH * HH + (size_t)(cb + jg * RPW) * HH + ig * 256 + lane * 8;

    // stage resident Wx rows 0..RES_X-1 (per warp): 1 uint4 per lane per row
    for (int r = 0; r < RES_X; ++r)
        sres[(w * RES_X + r) * 32 + lane] = *reinterpret_cast<const uint4*>(pWx + (size_t)r * HH);
    __syncthreads();

    for (int t = 0; t < T_STEPS; ++t) {
        const float* st  = states + (size_t)t * NN * 2 * HH;
        float*       stn = states + (size_t)(t + 1) * NN * 2 * HH;
        const int par = t & 1;

        float acc[8];
        #pragma unroll
        for (int k = 0; k < 8; ++k) acc[k] = 0.0f;

        // ---- Wh partial: local hy chunk, streamed from L2 (covers wait) ----
        #pragma unroll 8
        for (int r = 0; r < RPW; ++r) {
            const float v = sh_hy[jg * RPW + r];
            fma8(acc, *reinterpret_cast<const uint4*>(pWh + (size_t)r * HH), v);
        }

        // ---- chunk wait: all 64 blocks of chunk group c stored hy(t) -------
        if (t > 0) {
            if (tid == 0) spin_until(&g_chunk_cnt[c * 32], 64u * (unsigned)t);
            __syncthreads();                                        // bar A
        }

        // ---- C-mix for own 128 j's (4-way m-split over 512 threads) --------
        {
            const int jloc = tid & 127;
            const int mg   = tid >> 7;
            float cm = 0.0f;
            if (t > 0) {
                const float* sp = st + (size_t)(2 * mg * 16) * HH + cb + jloc;
                #pragma unroll 8
                for (int m = 0; m < 16; ++m)
                    cm += sh_C[mg * 16 + m] * sp[(size_t)m * 2 * HH];
            }
            sh_cm[mg * 128 + jloc] = cm;
        }
        __syncthreads();                                            // bar B

        // ---- hoisted streamed-Wx loads (static addresses; latency overlaps
        //      the ins-combine + barrier below) ------------------------------
        uint4 pf[4];
        #pragma unroll
        for (int r = 0; r < 4; ++r)
            pf[r] = *reinterpret_cast<const uint4*>(pWx + (size_t)(RES_X + r) * HH);

        if (tid < 128) {
            const float v = (t > 0)
                ? (sh_cm[tid] + sh_cm[128 + tid] + sh_cm[256 + tid] + sh_cm[384 + tid]) * xv
                : 0.0f;
            sh_ins[tid] = v;
            ins[((size_t)(t + 1) * NN + n) * HH + cb + tid] = v;    // output only
        }
        __syncthreads();                                            // bar C

        // ---- Wx partial: last 2 streamed loads, resident, hoisted, tail ----
        {
            const uint4 s14 = *reinterpret_cast<const uint4*>(pWx + (size_t)14 * HH);
            const uint4 s15 = *reinterpret_cast<const uint4*>(pWx + (size_t)15 * HH);

            #pragma unroll
            for (int r = 0; r < RES_X; ++r) {
                const float v = sh_ins[jg * RPW + r];
                fma8(acc, sres[(w * RES_X + r) * 32 + lane], v);
            }
            #pragma unroll
            for (int r = 0; r < 4; ++r)
                fma8(acc, pf[r], sh_ins[jg * RPW + RES_X + r]);
            fma8(acc, s14, sh_ins[jg * RPW + 14]);
            fma8(acc, s15, sh_ins[jg * RPW + 15]);
        }

        // ---- single-round reduce: warp w writes 256 partials, sum 8 --------
        {
            float* pp = sh_red + w * 256 + lane * 8;
            *reinterpret_cast<float4*>(pp)     = make_float4(acc[0], acc[1], acc[2], acc[3]);
            *reinterpret_cast<float4*>(pp + 4) = make_float4(acc[4], acc[5], acc[6], acc[7]);
        }
        __syncthreads();                                            // bar D
        {
            const int oi = tid >> 8;          // output i-half
            const int ii = tid & 255;
            float s = 0.0f;
            #pragma unroll
            for (int k = 0; k < 8; ++k) s += sh_red[(oi * 8 + k) * 256 + ii];
            g_partial[((size_t)(par * NN + n) * 4 + c) * HH + tid] = s;
        }
        __syncthreads();                                            // bar F
        if (tid == 0) {
            arrive_rel(&g_part_cnt[n]);
            spin_until(&g_part_cnt[n], 4u * (unsigned)(t + 1));
        }
        __syncthreads();                                            // bar G

        // ---- combine 4 partials (fixed order), update own i-chunk ----------
        if (tid < 128) {
            const float* gp = g_partial + (size_t)(par * NN + n) * 4 * HH;
            float s = bias;
            #pragma unroll
            for (int cc = 0; cc < 4; ++cc) s += gp[cc * HH + cb + tid];
            const float hy   = sh_hy[tid];
            const float hz_n = hz_r + DT_C * (tanhf(s) - hy - hz_r);   // GAMMA=EPS=1
            const float hy_n = hy + DT_C * hz_n;
            hz_r = hz_n;
            stn[(n * 2 + 0) * HH + cb + tid] = hy_n;
            stn[(n * 2 + 1) * HH + cb + tid] = hz_n;
            sh_hy[tid] = hy_n;
            if (t + 1 < T_STEPS)
                xv = x[((size_t)(t + 1) * NN + n) * HH + cb + tid];
            // early publish: combine warps sync among themselves, then release
            asm volatile("bar.sync 1, 128;" ::: "memory");
            if (tid == 0) arrive_rel(&g_chunk_cnt[c * 32]);
        }
        __syncthreads();                                            // bar H
    }
}

// ---------------------------------------------------------------------------
extern "C" void kernel_launch(void* const* d_in, const int* in_sizes, int n_in,
                              void* d_out, int out_size)
{
    const float* x   = (const float*)d_in[0];   // (256, 64, 512)
    const float* C   = (const float*)d_in[1];   // (64, 64)
    const float* Wh  = (const float*)d_in[2];   // (64, 512, 512)
    const float* Wx  = (const float*)d_in[3];   // (64, 512, 512)
    const float* b   = (const float*)d_in[4];   // (64, 512)
    const float* s0  = (const float*)d_in[5];   // (64, 2, 512)

    float* out    = (float*)d_out;
    float* states = out;                                          // (257,64,2,512)
    float* ins    = out + (size_t)(T_STEPS + 1) * NN * 2 * HH;    // (257,64,512)

    cudaFuncSetAttribute(rnn_kernel, cudaFuncAttributeMaxDynamicSharedMemorySize, DYN_SMEM);

    dim3 tb(32, 8, 1), tg(16, 16, NN);
    convert_transpose_kernel<<<tg, tb>>>(Wh, 0);
    convert_transpose_kernel<<<tg, tb>>>(Wx, 1);
    init_out_kernel<<<(NN * 2 * HH + 255) / 256, 256>>>(x, s0, states, ins);
    rnn_kernel<<<NBLK, NTHR, DYN_SMEM>>>(x, C, b, states, ins);
}

// round 17
// speedup vs baseline: 1.2224x; 1.2224x over previous
#include <cuda_runtime.h>
#include <cuda_fp16.h>

#define T_STEPS 256
#define NN      64
#define HH      512
#define DT_C    0.01f
#define NBLK    256
#define NTHR    512
#define NWARP   16
#define RPW     16                                  // j-rows per warp (256-i wide)
#define RES_X   11                                  // resident Wx rows per warp
#define DYN_SMEM (NWARP * RES_X * 32 * 16)          // 16*11*512 = 90112 B

// fp16 transposed weights: layout [n][j][i]
__device__ __half g_Wh[(size_t)NN * HH * HH];
__device__ __half g_Wx[(size_t)NN * HH * HH];
// partial-sum exchange, parity double-buffered: [par][n][c][i]
__device__ float g_partial[2 * NN * 4 * HH];
__device__ unsigned g_chunk_cnt[4 * 32];   // per-chunk hy counters (128B apart)
__device__ unsigned g_part_cnt[NN];        // +4 per neuron per step

// ---------------------------------------------------------------------------
__device__ __forceinline__ void arrive_rel(unsigned* ctr)
{
    asm volatile("red.release.gpu.add.u32 [%0], 1;" :: "l"(ctr) : "memory");
}
__device__ __forceinline__ unsigned ld_acq(unsigned* ctr)
{
    unsigned v;
    asm volatile("ld.acquire.gpu.u32 %0, [%1];" : "=r"(v) : "l"(ctr) : "memory");
    return v;
}
__device__ __forceinline__ void spin_until(unsigned* ctr, unsigned target)
{
    while (ld_acq(ctr) < target) { }   // tight poll: dependent-load cadence ~L2 RT
}

// ---------------------------------------------------------------------------
// fp32 [n][i][j]  ->  fp16 [n][j][i]   (transpose + convert, tiled)
// ---------------------------------------------------------------------------
__global__ void convert_transpose_kernel(const float* __restrict__ src, int which)
{
    __shared__ float tile[32][33];
    __half* dst = which ? g_Wx : g_Wh;
    const int nmat = blockIdx.z;
    const float* s = src + (size_t)nmat * HH * HH;
    __half*      d = dst + (size_t)nmat * HH * HH;
    const int x0 = blockIdx.x * 32;
    const int y0 = blockIdx.y * 32;
    #pragma unroll
    for (int k = threadIdx.y; k < 32; k += 8)
        tile[k][threadIdx.x] = s[(size_t)(y0 + k) * HH + x0 + threadIdx.x];
    __syncthreads();
    #pragma unroll
    for (int k = threadIdx.y; k < 32; k += 8)
        d[(size_t)(x0 + k) * HH + y0 + threadIdx.x] = __float2half_rn(tile[threadIdx.x][k]);
}

// ---------------------------------------------------------------------------
__global__ void init_out_kernel(const float* __restrict__ x,
                                const float* __restrict__ init_states,
                                float* __restrict__ states,
                                float* __restrict__ ins)
{
    const int i = blockIdx.x * blockDim.x + threadIdx.x;
    if (i < NN * 2 * HH) states[i] = init_states[i];
    if (i < NN * HH)     ins[i]    = x[i];
    if (i < NN)          g_part_cnt[i] = 0;
    if (i < 4 * 32)      g_chunk_cnt[i] = 0;
}

// ---------------------------------------------------------------------------
__device__ __forceinline__ void fma8(float* acc, uint4 a, float v)
{
    float2 f;
    f = __half22float2(*reinterpret_cast<__half2*>(&a.x)); acc[0] += f.x * v; acc[1] += f.y * v;
    f = __half22float2(*reinterpret_cast<__half2*>(&a.y)); acc[2] += f.x * v; acc[3] += f.y * v;
    f = __half22float2(*reinterpret_cast<__half2*>(&a.z)); acc[4] += f.x * v; acc[5] += f.y * v;
    f = __half22float2(*reinterpret_cast<__half2*>(&a.w)); acc[6] += f.x * v; acc[7] += f.y * v;
}

// ---------------------------------------------------------------------------
// persistent RNN, fully j-partitioned (R15 topology): 256 blocks = 4 per
// neuron, 2 blocks/SM, 512 threads.  Warp w = (ig = w>>3, jg = w&7) covers
// 16 j-rows x 256 i-outputs (acc[8]); single-round reduce over 8 partials.
// R17: RES_X 10->11 (one fewer streamed row on the post-ins path) and tight
// counter polling.  No register prefetch across barriers (R13/R16 lesson).
// ---------------------------------------------------------------------------
__global__ void __launch_bounds__(NTHR, 2) rnn_kernel(
    const float* __restrict__ x,      // [T][N][H]
    const float* __restrict__ C,      // [N][N]
    const float* __restrict__ b,      // [N][H]
    float* __restrict__ states,       // [T+1][N][2][H]
    float* __restrict__ ins)          // [T+1][N][H]
{
    extern __shared__ __align__(16) unsigned char dynsmem[];
    uint4* sres = reinterpret_cast<uint4*>(dynsmem);

    __shared__ __align__(16) float sh_red[NWARP * 256];  // 16 KB reduce buffer
    __shared__ float sh_hy[128];
    __shared__ float sh_ins[128];
    __shared__ float sh_C[NN];
    __shared__ float sh_cm[4 * 128];

    const int bid  = blockIdx.x;
    const int n    = bid >> 2;
    const int c    = bid & 3;
    const int cb   = c * 128;
    const int tid  = threadIdx.x;
    const int w    = tid >> 5;
    const int lane = tid & 31;
    const int ig   = w >> 3;          // i-half: 0 or 1 (256 outputs)
    const int jg   = w & 7;           // j-group: 16 rows

    if (tid < NN) sh_C[tid] = C[n * NN + tid];
    const float bias = (tid < 128) ? b[n * HH + cb + tid] : 0.0f;
    float hz_r = (tid < 128) ? states[(n * 2 + 1) * HH + cb + tid] : 0.0f;
    if (tid < 128) sh_hy[tid] = states[(n * 2 + 0) * HH + cb + tid];
    float xv = (tid < 128) ? x[(size_t)n * HH + cb + tid] : 0.0f;

    // warp (ig,jg): j-rows cb + jg*16 .. +15, i-range ig*256 + lane*8
    const __half* pWh = g_Wh + (size_t)n * HH * HH + (size_t)(cb + jg * RPW) * HH + ig * 256 + lane * 8;
    const __half* pWx = g_Wx + (size_t)n * HH * HH + (size_t)(cb + jg * RPW) * HH + ig * 256 + lane * 8;

    // stage resident Wx rows 0..RES_X-1 (per warp): 1 uint4 per lane per row
    for (int r = 0; r < RES_X; ++r)
        sres[(w * RES_X + r) * 32 + lane] = *reinterpret_cast<const uint4*>(pWx + (size_t)r * HH);
    __syncthreads();

    for (int t = 0; t < T_STEPS; ++t) {
        const float* st  = states + (size_t)t * NN * 2 * HH;
        float*       stn = states + (size_t)(t + 1) * NN * 2 * HH;
        const int par = t & 1;

        float acc[8];
        #pragma unroll
        for (int k = 0; k < 8; ++k) acc[k] = 0.0f;

        // ---- Wh partial: local hy chunk, streamed from L2 (covers wait) ----
        #pragma unroll 4
        for (int r = 0; r < RPW; ++r) {
            const float v = sh_hy[jg * RPW + r];
            fma8(acc, *reinterpret_cast<const uint4*>(pWh + (size_t)r * HH), v);
        }

        // ---- chunk wait: all 64 blocks of chunk group c stored hy(t) -------
        if (t > 0) {
            if (tid == 0) spin_until(&g_chunk_cnt[c * 32], 64u * (unsigned)t);
            __syncthreads();                                        // bar A
        }

        // ---- C-mix for own 128 j's (4-way m-split over 512 threads) --------
        {
            const int jloc = tid & 127;
            const int mg   = tid >> 7;
            float cm = 0.0f;
            if (t > 0) {
                const float* sp = st + (size_t)(2 * mg * 16) * HH + cb + jloc;
                #pragma unroll 8
                for (int m = 0; m < 16; ++m)
                    cm += sh_C[mg * 16 + m] * sp[(size_t)m * 2 * HH];
            }
            sh_cm[mg * 128 + jloc] = cm;
        }
        __syncthreads();                                            // bar B
        if (tid < 128) {
            const float v = (t > 0)
                ? (sh_cm[tid] + sh_cm[128 + tid] + sh_cm[256 + tid] + sh_cm[384 + tid]) * xv
                : 0.0f;
            sh_ins[tid] = v;
            ins[((size_t)(t + 1) * NN + n) * HH + cb + tid] = v;    // output only
        }
        __syncthreads();                                            // bar C

        // ---- Wx partial: streamed tail first (LDG MLP), then resident ------
        #pragma unroll
        for (int r = RES_X; r < RPW; ++r) {
            const float v = sh_ins[jg * RPW + r];
            fma8(acc, *reinterpret_cast<const uint4*>(pWx + (size_t)r * HH), v);
        }
        #pragma unroll
        for (int r = 0; r < RES_X; ++r) {
            const float v = sh_ins[jg * RPW + r];
            fma8(acc, sres[(w * RES_X + r) * 32 + lane], v);
        }

        // ---- single-round reduce: warp w writes 256 partials, sum 8 --------
        {
            float* pp = sh_red + w * 256 + lane * 8;
            *reinterpret_cast<float4*>(pp)     = make_float4(acc[0], acc[1], acc[2], acc[3]);
            *reinterpret_cast<float4*>(pp + 4) = make_float4(acc[4], acc[5], acc[6], acc[7]);
        }
        __syncthreads();                                            // bar D
        {
            const int oi = tid >> 8;          // output i-half
            const int ii = tid & 255;
            float s = 0.0f;
            #pragma unroll
            for (int k = 0; k < 8; ++k) s += sh_red[(oi * 8 + k) * 256 + ii];
            g_partial[((size_t)(par * NN + n) * 4 + c) * HH + tid] = s;
        }
        __syncthreads();                                            // bar F
        if (tid == 0) {
            arrive_rel(&g_part_cnt[n]);
            spin_until(&g_part_cnt[n], 4u * (unsigned)(t + 1));
        }
        __syncthreads();                                            // bar G

        // ---- combine 4 partials (fixed order), update own i-chunk ----------
        if (tid < 128) {
            const float* gp = g_partial + (size_t)(par * NN + n) * 4 * HH;
            float s = bias;
            #pragma unroll
            for (int cc = 0; cc < 4; ++cc) s += gp[cc * HH + cb + tid];
            const float hy   = sh_hy[tid];
            const float hz_n = hz_r + DT_C * (tanhf(s) - hy - hz_r);   // GAMMA=EPS=1
            const float hy_n = hy + DT_C * hz_n;
            hz_r = hz_n;
            stn[(n * 2 + 0) * HH + cb + tid] = hy_n;
            stn[(n * 2 + 1) * HH + cb + tid] = hz_n;
            sh_hy[tid] = hy_n;
            if (t + 1 < T_STEPS)
                xv = x[((size_t)(t + 1) * NN + n) * HH + cb + tid];
        }
        __syncthreads();                                            // bar H
        if (tid == 0) arrive_rel(&g_chunk_cnt[c * 32]);
    }
}

// ---------------------------------------------------------------------------
extern "C" void kernel_launch(void* const* d_in, const int* in_sizes, int n_in,
                              void* d_out, int out_size)
{
    const float* x   = (const float*)d_in[0];   // (256, 64, 512)
    const float* C   = (const float*)d_in[1];   // (64, 64)
    const float* Wh  = (const float*)d_in[2];   // (64, 512, 512)
    const float* Wx  = (const float*)d_in[3];   // (64, 512, 512)
    const float* b   = (const float*)d_in[4];   // (64, 512)
    const float* s0  = (const float*)d_in[5];   // (64, 2, 512)

    float* out    = (float*)d_out;
    float* states = out;                                          // (257,64,2,512)
    float* ins    = out + (size_t)(T_STEPS + 1) * NN * 2 * HH;    // (257,64,512)

    cudaFuncSetAttribute(rnn_kernel, cudaFuncAttributeMaxDynamicSharedMemorySize, DYN_SMEM);

    dim3 tb(32, 8, 1), tg(16, 16, NN);
    convert_transpose_kernel<<<tg, tb>>>(Wh, 0);
    convert_transpose_kernel<<<tg, tb>>>(Wx, 1);
    init_out_kernel<<<(NN * 2 * HH + 255) / 256, 256>>>(x, s0, states, ins);
    rnn_kernel<<<NBLK, NTHR, DYN_SMEM>>>(x, C, b, states, ins);
}